// round 17
// baseline (speedup 1.0000x reference)
#include <cuda_runtime.h>
#include <cuda_fp16.h>
#include <cstdint>

// MonarchLayer: y[b, l*64+j] = sum_k L[j,k,l] * t1[b,k,j] + bias,
//               t1[b,k,j]    = sum_i x[b,k*64+i] * R[k,i,j]
// Two-stage HMMA (m16n8k16 fp16/fp32), fp16 intermediate in transpose-friendly
// layout T1t[b][jg][k][jw] (jg=j>>3, jw=j&7).
// k1-v3: CTA = 128 rows x 2 adjacent kblks -> flush writes full 32B sectors
//        (kills T1t write amplification).
// k2: R14 version (measured 180us, regs 127) + __stwt out stores.
// NOTE: harness ptxas targets sm_103 (no tcgen05); HMMA only.

#define BATCH 16384
#define DIMN  4096

// ---------------- device scratch (static, allocation-free) ----------------
__device__ __align__(16) __half g_T1[(size_t)BATCH * DIMN];  // 128 MB, layout [b][jg][k][jw]
__device__ __align__(16) __half g_Rh[64 * 64 * 64];          // R fp16 [k][i][j]
__device__ __align__(16) __half g_Lh[64 * 64 * 64];          // L fp16 [j][k][l]

// ---------------- helpers ----------------
__device__ __forceinline__ uint32_t smem_u32(const void* p) {
    uint32_t a;
    asm("{ .reg .u64 t; cvta.to.shared.u64 t, %1; cvt.u32.u64 %0, t; }" : "=r"(a) : "l"(p));
    return a;
}
// XOR swizzle for 128B-row tiles, 16B granularity.
__device__ __forceinline__ int swz(int row, int chunk) {
    return row * 128 + (((chunk) ^ (row & 7)) << 4);
}
__device__ __forceinline__ void ldm_x4(uint32_t* r, uint32_t addr) {
    asm volatile("ldmatrix.sync.aligned.m8n8.x4.shared.b16 {%0,%1,%2,%3}, [%4];"
                 : "=r"(r[0]), "=r"(r[1]), "=r"(r[2]), "=r"(r[3]) : "r"(addr));
}
__device__ __forceinline__ void ldm_x2t(uint32_t* r, uint32_t addr) {
    asm volatile("ldmatrix.sync.aligned.m8n8.x2.trans.shared.b16 {%0,%1}, [%2];"
                 : "=r"(r[0]), "=r"(r[1]) : "r"(addr));
}
__device__ __forceinline__ void mma16816(float* c, const uint32_t* a, const uint32_t* b) {
    asm volatile("mma.sync.aligned.m16n8k16.row.col.f32.f16.f16.f32 "
                 "{%0,%1,%2,%3}, {%4,%5,%6,%7}, {%8,%9}, {%0,%1,%2,%3};"
                 : "+f"(c[0]), "+f"(c[1]), "+f"(c[2]), "+f"(c[3])
                 : "r"(a[0]), "r"(a[1]), "r"(a[2]), "r"(a[3]), "r"(b[0]), "r"(b[1]));
}

// ---------------- prep: cast L,R to fp16 ----------------
__global__ void monarch_prep(const float* __restrict__ L, const float* __restrict__ R) {
    int idx = blockIdx.x * blockDim.x + threadIdx.x;
    if (idx < 64 * 64 * 64) {
        g_Rh[idx] = __float2half_rn(R[idx]);
        g_Lh[idx] = __float2half_rn(L[idx]);
    }
}

// dummy launch: used twice so monarch_k1 lands at absolute launch index 3 (ncu slot)
__global__ void monarch_nop() {}

// ---------------- stage 1 v3: T1t[b][jg][k][jw] = sum_i x[b,k*64+i] * R[k,i,j] ----
// CTA: 128 rows x 2 kblks (k = kg*2 + kb), 256 threads, grid (32 kg, 128 bt).
// smem: sX 2 planes x [128r x 64i] fp16 = 32KB, sR 2 x [64i x 64j] = 16KB,
//       sO 2 x [128r x 64j] staging = 32KB  -> 80KB dynamic, 2 CTAs/SM.
// Flush: per (r, jg) thread writes kb0+kb1 granules = 32B contiguous -> FULL sectors.
#define K1_SX 0
#define K1_SR 32768
#define K1_SO 49152
#define K1_SMEM (K1_SO + 32768)

__global__ __launch_bounds__(256) void monarch_k1(const float* __restrict__ x) {
    extern __shared__ unsigned char smem[];
    unsigned char* sX = smem + K1_SX;
    unsigned char* sR = smem + K1_SR;
    unsigned char* sO = smem + K1_SO;

    const int kg = blockIdx.x;
    const size_t b0 = (size_t)blockIdx.y * 128;
    const int tid = threadIdx.x;

    // ---- load + convert x tile: 128 rows x 128 i (2 kblks)
#pragma unroll
    for (int it = 0; it < 8; it++) {
        int u = tid + it * 256;            // 0..2047
        int r = u >> 4, ic = u & 15;       // ic: 8-wide i chunk (2 kblks x 8)
        int kb = ic >> 3, c = ic & 7;
        const float4* gp = (const float4*)(x + (b0 + r) * DIMN + kg * 128 + ic * 8);
        float4 f0 = gp[0], f1 = gp[1];
        uint4 pk;
        __half2* hp = (__half2*)&pk;
        hp[0] = __floats2half2_rn(f0.x, f0.y);
        hp[1] = __floats2half2_rn(f0.z, f0.w);
        hp[2] = __floats2half2_rn(f1.x, f1.y);
        hp[3] = __floats2half2_rn(f1.z, f1.w);
        *(uint4*)(sX + kb * 16384 + swz(r, c)) = pk;
    }
    // ---- load R tiles: 2 planes x [64i x 64j]
#pragma unroll
    for (int it = 0; it < 4; it++) {
        int u = tid + it * 256;            // 0..1023
        int kb = u >> 9, wi = u & 511;
        int i = wi >> 3, c = wi & 7;
        uint4 v = *(const uint4*)(g_Rh + (size_t)(kg * 2 + kb) * 4096 + i * 64 + c * 8);
        *(uint4*)(sR + kb * 8192 + swz(i, c)) = v;
    }
    __syncthreads();

    const int w = tid >> 5, lane = tid & 31;
    const int rbase = w << 4;
    const int gr = lane >> 2, q = lane & 3;
    const int arow = rbase + ((lane >> 3) & 1) * 8 + (lane & 7);

    // ---- per kblk: proven R14-k1 compute + staging pattern
#pragma unroll
    for (int kb = 0; kb < 2; kb++) {
        const uint32_t sx32 = smem_u32(sX) + kb * 16384;
        const uint32_t sr32 = smem_u32(sR) + kb * 8192;
        unsigned char* sOk = sO + kb * 16384;

        float acc[8][4];
#pragma unroll
        for (int nt = 0; nt < 8; nt++)
#pragma unroll
            for (int c = 0; c < 4; c++) acc[nt][c] = 0.f;

#pragma unroll
        for (int kk = 0; kk < 4; kk++) {
            uint32_t a[4];
            ldm_x4(a, sx32 + swz(arow, 2 * kk + (lane >> 4)));
#pragma unroll
            for (int nt = 0; nt < 8; nt++) {
                uint32_t bf[2];
                ldm_x2t(bf, sr32 + swz(kk * 16 + (lane & 15), nt));
                mma16816(acc[nt], a, bf);
            }
        }
        // stage (conflict-free, same pattern as R1/R14 k1)
#pragma unroll
        for (int nt = 0; nt < 8; nt++) {
            int r0 = rbase + gr, r1 = r0 + 8;
            *(__half2*)(sOk + swz(r0, nt) + q * 4) = __floats2half2_rn(acc[nt][0], acc[nt][1]);
            *(__half2*)(sOk + swz(r1, nt) + q * 4) = __floats2half2_rn(acc[nt][2], acc[nt][3]);
        }
    }
    __syncthreads();

    // ---- flush: (r, jg) -> 32B contiguous (k = kg*2, kg*2+1) -> FULL sectors
#pragma unroll
    for (int i = 0; i < 4; i++) {
        int cid = tid + i * 256;           // 0..1023
        int r = cid >> 3, c = cid & 7;     // row, jg
        uint4 v0 = *(uint4*)(sO + swz(r, c));
        uint4 v1 = *(uint4*)(sO + 16384 + swz(r, c));
        __half* dst = g_T1 + (b0 + r) * DIMN + c * 512 + kg * 16;
        *(uint4*)dst = v0;
        *(uint4*)(dst + 8) = v1;
    }
}

// ---------------- stage 2 (R14, measured 180us): y = T1t x L + bias ----------------
// CTA: 32 batch rows x 8 j (one jg), 256 threads, grid (8 jg, 512 btiles).
// smem: sA 8 planes x [32r x 64k] = 32KB + sL 8 x [64k x 64l] = 64KB -> 96KB, 2 CTAs/SM.
#define K2_SMEM (32768 + 65536)

__global__ __launch_bounds__(256, 2) void monarch_k2(float* __restrict__ out,
                                                     const float* __restrict__ bias) {
    extern __shared__ unsigned char smem[];
    unsigned char* sA = smem;            // 8 planes * 4096 B
    unsigned char* sL = smem + 32768;    // 8 planes * 8192 B

    const int jg = blockIdx.x;                       // j in [jg*8, jg*8+8)
    const size_t b0 = (size_t)blockIdx.y * 32;
    const int tid = threadIdx.x;

    // ---- load 8 L[j] planes (coalesced)
#pragma unroll
    for (int i = 0; i < 16; i++) {
        int idx = tid + i * 256;          // 0..4095 chunks
        int p = idx >> 9, wi = idx & 511;
        int r = wi >> 3, c = wi & 7;
        uint4 v = *(const uint4*)(g_Lh + (size_t)(jg * 8 + p) * 4096 + r * 64 + c * 8);
        *(uint4*)(sL + p * 8192 + swz(r, c)) = v;
    }
    // ---- gather T1t: contiguous 32B per thread (k, k+1 granules), conflict-free scatter
#pragma unroll
    for (int i = 0; i < 4; i++) {
        int idx = tid + i * 256;          // 0..1023 ; r warp-uniform, kp = lane
        int r = idx >> 5, kp = idx & 31;
        int k = kp * 2;
        const __half* gp = g_T1 + (b0 + r) * DIMN + jg * 512 + k * 8;
        uint4 v0 = *(const uint4*)gp;          // k,   jw 0..7
        uint4 v1 = *(const uint4*)(gp + 8);    // k+1, jw 0..7
        const __half* h0 = (const __half*)&v0;
        const __half* h1 = (const __half*)&v1;
        int base = swz(r, k >> 3) + (k & 7) * 2;
#pragma unroll
        for (int s = 0; s < 8; s++)
            *(__half2*)(sA + s * 4096 + base) = __halves2half2(h0[s], h1[s]);
    }
    __syncthreads();

    const int w = tid >> 5, lane = tid & 31;
    const int rbase = (w & 1) << 4;       // 2 row strips of 16
    const int lh = w >> 1;                // 4 l-quarters, 2 ntiles each
    const int gr = lane >> 2, q = lane & 3;
    const uint32_t sa32 = smem_u32(sA), sl32 = smem_u32(sL);
    const int arow = rbase + ((lane >> 3) & 1) * 8 + (lane & 7);

#pragma unroll
    for (int g = 0; g < 2; g++) {         // j groups of 4 (caps accum regs)
        float st[2][4][4];                // [ntile][frag][jl]
#pragma unroll
        for (int jl = 0; jl < 4; jl++) {
            int jj = g * 4 + jl;
            uint32_t pa = sa32 + jj * 4096;
            uint32_t pb = sl32 + jj * 8192;
            uint32_t a[4][4];
#pragma unroll
            for (int kk = 0; kk < 4; kk++)
                ldm_x4(a[kk], pa + swz(arow, 2 * kk + (lane >> 4)));
#pragma unroll
            for (int nt = 0; nt < 2; nt++) {
                int ntg = lh * 2 + nt;
                float acc[4] = {0.f, 0.f, 0.f, 0.f};
#pragma unroll
                for (int kk = 0; kk < 4; kk++) {
                    uint32_t bf[2];
                    ldm_x2t(bf, pb + swz(kk * 16 + (lane & 15), ntg));
                    mma16816(acc, a[kk], bf);
                }
                st[nt][0][jl] = acc[0];
                st[nt][1][jl] = acc[1];
                st[nt][2][jl] = acc[2];
                st[nt][3][jl] = acc[3];
            }
        }
        // epilogue for this j-group: float4 (4 consecutive j) per (row, l), streaming
#pragma unroll
        for (int nt = 0; nt < 2; nt++) {
            int ntg = lh * 2 + nt;
#pragma unroll
            for (int c = 0; c < 4; c++) {
                int row = (int)b0 + rbase + gr + ((c & 2) ? 8 : 0);
                int l = ntg * 8 + q * 2 + (c & 1);
                int col = l * 64 + jg * 8 + g * 4;
                float4 bv = __ldg((const float4*)(bias + col));
                float4 v = make_float4(st[nt][c][0] + bv.x, st[nt][c][1] + bv.y,
                                       st[nt][c][2] + bv.z, st[nt][c][3] + bv.w);
                __stwt((float4*)(out + (size_t)row * DIMN + col), v);
            }
        }
    }
}

// ---------------- launch ----------------
extern "C" void kernel_launch(void* const* d_in, const int* in_sizes, int n_in,
                              void* d_out, int out_size) {
    (void)in_sizes; (void)n_in; (void)out_size;
    const float* x    = (const float*)d_in[0];
    const float* L    = (const float*)d_in[1];
    const float* R    = (const float*)d_in[2];
    const float* bias = (const float*)d_in[3];
    float* out = (float*)d_out;

    cudaFuncSetAttribute(monarch_k1, cudaFuncAttributeMaxDynamicSharedMemorySize, K1_SMEM);
    cudaFuncSetAttribute(monarch_k2, cudaFuncAttributeMaxDynamicSharedMemorySize, K2_SMEM);

    monarch_prep<<<1024, 256>>>(L, R);                         // launch 0
    monarch_nop<<<1, 32>>>();                                  // launch 1 (shim)
    monarch_nop<<<1, 32>>>();                                  // launch 2 (shim)
    monarch_k1<<<dim3(32, 128), 256, K1_SMEM>>>(x);            // launch 3 -> profiled
    monarch_k2<<<dim3(8, 512), 256, K2_SMEM>>>(out, bias);     // launch 4
}